// round 16
// baseline (speedup 1.0000x reference)
#include <cuda_runtime.h>
#include <cuda_bf16.h>
#include <cuda_fp16.h>
#include <cstdint>
#include <cstddef>

#define BATCH 8
#define PB    4194304
#define KD    16384
#define SPLIT 8

__device__ float g_part[(size_t)SPLIT * BATCH * 65536];
__device__ float g_red[(size_t)BATCH * 65536];
__device__ float g_sr[BATCH * 256];
__device__ float g_sx[BATCH * 256];
__device__ float g_f [BATCH * 65536];
__device__ __half g_Uh[BATCH * 65536];
__device__ float g_bp[BATCH * 4 * 256];
__device__ __half g_y4h[(size_t)BATCH * PB];

static __device__ __forceinline__ void hmma_bf(float* d, const uint32_t* a, const uint32_t* b) {
    asm volatile("mma.sync.aligned.m16n8k16.row.col.f32.bf16.bf16.f32 "
        "{%0,%1,%2,%3}, {%4,%5,%6,%7}, {%8,%9}, {%0,%1,%2,%3};"
        : "+f"(d[0]), "+f"(d[1]), "+f"(d[2]), "+f"(d[3])
        : "r"(a[0]), "r"(a[1]), "r"(a[2]), "r"(a[3]), "r"(b[0]), "r"(b[1]));
}
static __device__ __forceinline__ void hmma_hf(float* d, const uint32_t* a, const uint32_t* b) {
    asm volatile("mma.sync.aligned.m16n8k16.row.col.f32.f16.f16.f32 "
        "{%0,%1,%2,%3}, {%4,%5,%6,%7}, {%8,%9}, {%0,%1,%2,%3};"
        : "+f"(d[0]), "+f"(d[1]), "+f"(d[2]), "+f"(d[3])
        : "r"(a[0]), "r"(a[1]), "r"(a[2]), "r"(a[3]), "r"(b[0]), "r"(b[1]));
}
static __device__ __forceinline__ void pk(float x, float y, uint32_t& h, uint32_t& e) {
    uint32_t hv;
    asm("cvt.rn.bf16x2.f32 %0, %1, %2;" : "=r"(hv) : "f"(y), "f"(x));
    float hx = __uint_as_float(hv << 16);
    float hy = __uint_as_float(hv & 0xFFFF0000u);
    uint32_t ev;
    float ex = x - hx, ey = y - hy;
    asm("cvt.rn.bf16x2.f32 %0, %1, %2;" : "=r"(ev) : "f"(ey), "f"(ex));
    h = hv; e = ev;
}

__global__ void kz() {
    int i = blockIdx.x * 256 + threadIdx.x;
    g_sr[i] = 0.f; g_sx[i] = 0.f;
}

// ---- K1: G = ref2 @ x2^T, bf16 3-product, split-K, fused rowsums ----
__global__ void __launch_bounds__(256, 2) k1(const float* __restrict__ ref, const float* __restrict__ x) {
    extern __shared__ uint32_t smu[];
    uint32_t* pAH = smu;         uint32_t* pAE = smu + 4608;
    uint32_t* pBH = smu + 9216;  uint32_t* pBE = smu + 13824;
    const int t = threadIdx.x, lane = t & 31, wid = t >> 5;
    const int wm = wid >> 2, wn = wid & 3, g = lane >> 2, tg = lane & 3;
    const int mt_ = blockIdx.x >> 1, nt_ = blockIdx.x & 1, b = blockIdx.y, sp = blockIdx.z;
    const int m0 = mt_ * 128, n0 = nt_ * 128;
    const float* Ag = ref + (size_t)b * PB + (size_t)m0 * KD + sp * 2048;
    const float* Bg = x   + (size_t)b * PB + (size_t)n0 * KD + sp * 2048;
    const int r = t >> 1, kb = (t & 1) * 32;
    float sa = 0.f, sx = 0.f;
    float acc[4][4][4];
#pragma unroll
    for (int i = 0; i < 4; i++)
#pragma unroll
        for (int j = 0; j < 4; j++)
#pragma unroll
            for (int q = 0; q < 4; q++) acc[i][j][q] = 0.f;

    for (int ck = 0; ck < 32; ck++) {
        const float4* ap = (const float4*)(Ag + (size_t)r * KD + ck * 64 + kb);
        const float4* bp = (const float4*)(Bg + (size_t)r * KD + ck * 64 + kb);
        float4 va[4], vb[4];
#pragma unroll
        for (int q = 0; q < 4; q++) { va[q] = ap[q]; vb[q] = bp[q]; }
        __syncthreads();
#pragma unroll
        for (int q = 0; q < 4; q++) {
            sa += (va[q].x + va[q].y) + (va[q].z + va[q].w);
            sx += (vb[q].x + vb[q].y) + (vb[q].z + vb[q].w);
            uint32_t h0, e0, h1, e1;
            int ix = r * 36 + ((kb + q * 4) >> 1);
            pk(va[q].x, va[q].y, h0, e0); pk(va[q].z, va[q].w, h1, e1);
            pAH[ix] = h0; pAH[ix + 1] = h1; pAE[ix] = e0; pAE[ix + 1] = e1;
            pk(vb[q].x, vb[q].y, h0, e0); pk(vb[q].z, vb[q].w, h1, e1);
            pBH[ix] = h0; pBH[ix + 1] = h1; pBE[ix] = e0; pBE[ix + 1] = e1;
        }
#pragma unroll
        for (int q = 0; q < 4; q++) { va[q] = ap[4 + q]; vb[q] = bp[4 + q]; }
#pragma unroll
        for (int q = 0; q < 4; q++) {
            sa += (va[q].x + va[q].y) + (va[q].z + va[q].w);
            sx += (vb[q].x + vb[q].y) + (vb[q].z + vb[q].w);
            uint32_t h0, e0, h1, e1;
            int ix = r * 36 + ((kb + (4 + q) * 4) >> 1);
            pk(va[q].x, va[q].y, h0, e0); pk(va[q].z, va[q].w, h1, e1);
            pAH[ix] = h0; pAH[ix + 1] = h1; pAE[ix] = e0; pAE[ix + 1] = e1;
            pk(vb[q].x, vb[q].y, h0, e0); pk(vb[q].z, vb[q].w, h1, e1);
            pBH[ix] = h0; pBH[ix + 1] = h1; pBE[ix] = e0; pBE[ix + 1] = e1;
        }
        __syncthreads();
#pragma unroll
        for (int kk = 0; kk < 4; kk++) {
            const int kh = kk * 8;
            uint32_t Ah[4][4], Ae[4][4], Bh[4][2], Be[4][2];
#pragma unroll
            for (int mt = 0; mt < 4; mt++) {
                int mr = wm * 64 + mt * 16;
                Ah[mt][0] = pAH[(mr + g) * 36 + kh + tg];
                Ah[mt][1] = pAH[(mr + g + 8) * 36 + kh + tg];
                Ah[mt][2] = pAH[(mr + g) * 36 + kh + tg + 4];
                Ah[mt][3] = pAH[(mr + g + 8) * 36 + kh + tg + 4];
                Ae[mt][0] = pAE[(mr + g) * 36 + kh + tg];
                Ae[mt][1] = pAE[(mr + g + 8) * 36 + kh + tg];
                Ae[mt][2] = pAE[(mr + g) * 36 + kh + tg + 4];
                Ae[mt][3] = pAE[(mr + g + 8) * 36 + kh + tg + 4];
            }
#pragma unroll
            for (int nt = 0; nt < 4; nt++) {
                int nr = wn * 32 + nt * 8 + g;
                Bh[nt][0] = pBH[nr * 36 + kh + tg];
                Bh[nt][1] = pBH[nr * 36 + kh + tg + 4];
                Be[nt][0] = pBE[nr * 36 + kh + tg];
                Be[nt][1] = pBE[nr * 36 + kh + tg + 4];
            }
#pragma unroll
            for (int mt = 0; mt < 4; mt++)
#pragma unroll
                for (int nt = 0; nt < 4; nt++) {
                    hmma_bf(acc[mt][nt], Ah[mt], Bh[nt]);
                    hmma_bf(acc[mt][nt], Ah[mt], Be[nt]);
                    hmma_bf(acc[mt][nt], Ae[mt], Bh[nt]);
                }
        }
    }
    sa += __shfl_xor_sync(0xffffffffu, sa, 1);
    sx += __shfl_xor_sync(0xffffffffu, sx, 1);
    if ((t & 1) == 0) {
        if (nt_ == 0) atomicAdd(&g_sr[b * 256 + m0 + r], sa);
        if (mt_ == 0) atomicAdd(&g_sx[b * 256 + n0 + r], sx);
    }
    float* op = g_part + ((size_t)sp * BATCH + b) * 65536;
#pragma unroll
    for (int mt = 0; mt < 4; mt++)
#pragma unroll
        for (int nt = 0; nt < 4; nt++) {
            int row = m0 + wm * 64 + mt * 16 + g;
            int col = n0 + wn * 32 + nt * 8 + tg * 2;
            int rp = (row & 3) * 64 + (row >> 2);
            int cp = (col & 3) * 64 + (col >> 2);
            op[(size_t)rp * 256 + cp]            = acc[mt][nt][0];
            op[(size_t)rp * 256 + cp + 64]       = acc[mt][nt][1];
            op[(size_t)(rp + 2) * 256 + cp]      = acc[mt][nt][2];
            op[(size_t)(rp + 2) * 256 + cp + 64] = acc[mt][nt][3];
        }
}

// ---- KRED: g_red = sum_s g_part[s]  (grid-strided, 8-way MLP) ----
__global__ void kred() {
    const size_t i = ((size_t)blockIdx.x * 256 + threadIdx.x) * 4;   // float4 index base
    float4 a = *(const float4*)(g_part + i);
#pragma unroll
    for (int s = 1; s < SPLIT; s++) {
        float4 v = *(const float4*)(g_part + (size_t)s * (BATCH * 65536) + i);
        a.x += v.x; a.y += v.y; a.z += v.z; a.w += v.w;
    }
    *(float4*)(g_red + i) = a;
}

// ---- K2a: f = Wth' G Wph'^T + bias rank-1 (reads reduced G) ----
__global__ void k2a_f(const float* __restrict__ wth, const float* __restrict__ bth,
                      const float* __restrict__ wph, const float* __restrict__ bph) {
    const int hb1 = blockIdx.x >> 2, hb2 = blockIdx.x & 3, b = blockIdx.y;
    __shared__ float S[64][64], T[64][64], ths[64], phs[64];
    const int t = threadIdx.x;
    for (int idx = t; idx < 4096; idx += 256) {
        int c = idx >> 6, cp = idx & 63;
        S[c][cp] = g_red[(size_t)b * 65536 + (size_t)(hb1 * 64 + c) * 256 + hb2 * 64 + cp];
    }
    __syncthreads();
    for (int idx = t; idx < 4096; idx += 256) {
        int ci = idx >> 6, cp = idx & 63;
        float a = 0.f;
#pragma unroll
        for (int c = 0; c < 64; c++) a = fmaf(__ldg(&wth[ci * 64 + c]), S[c][cp], a);
        T[ci][cp] = a;
    }
    __syncthreads();
    if (t < 64) {
        float a = 0.f;
        for (int c = 0; c < 64; c++) a = fmaf(wth[t * 64 + c], g_sr[b * 256 + c * 4 + hb1], a);
        ths[t] = a;
    } else if (t < 128) {
        int ci = t - 64;
        float a = 0.f;
        for (int cp = 0; cp < 64; cp++) a = fmaf(wph[ci * 64 + cp], g_sx[b * 256 + cp * 4 + hb2], a);
        phs[ci] = a;
    }
    for (int idx = t; idx < 4096; idx += 256) S[idx & 63][idx >> 6] = wph[idx];
    __syncthreads();
    for (int idx = t; idx < 4096; idx += 256) {
        int c1 = idx >> 6, c2 = idx & 63;
        float a = 0.f;
#pragma unroll
        for (int cp = 0; cp < 64; cp++) a = fmaf(T[c1][cp], S[cp][c2], a);
        float bt = __ldg(&bth[c1]), bp = __ldg(&bph[c2]);
        a += bt * phs[c2] + ths[c1] * bp + 16384.f * bt * bp;
        g_f[(size_t)b * 65536 + (size_t)(c1 * 4 + hb1) * 256 + hb2 * 64 + c2] = a;
    }
}

__global__ void k2b_softmax() {
    const int b = blockIdx.y, col = blockIdx.x * 8 + (threadIdx.x >> 5), lane = threadIdx.x & 31;
    float* F = g_f + (size_t)b * 65536;
    float v[8];
#pragma unroll
    for (int s = 0; s < 8; s++) v[s] = F[(s * 32 + lane) * 256 + col];
    float m = v[0];
#pragma unroll
    for (int s = 1; s < 8; s++) m = fmaxf(m, v[s]);
#pragma unroll
    for (int o = 16; o > 0; o >>= 1) m = fmaxf(m, __shfl_xor_sync(0xffffffffu, m, o));
    float sum = 0.f;
#pragma unroll
    for (int s = 0; s < 8; s++) { v[s] = expf(v[s] - m); sum += v[s]; }
#pragma unroll
    for (int o = 16; o > 0; o >>= 1) sum += __shfl_xor_sync(0xffffffffu, sum, o);
    float rcp = 1.f / sum;
#pragma unroll
    for (int s = 0; s < 8; s++) F[(s * 32 + lane) * 256 + col] = v[s] * rcp;
}

// ---- K2c: U = fdiv * Wg-blockdiag -> fp16 (coalesced); beta partials ----
__global__ void k2c_u(const float* __restrict__ wg, const float* __restrict__ bg) {
    const int hb2 = blockIdx.x, b = blockIdx.y;
    __shared__ float wgs[64][64];
    for (int idx = threadIdx.x; idx < 4096; idx += 256) wgs[idx >> 6][idx & 63] = wg[idx];
    __syncthreads();
    const int i = threadIdx.x;
    const float* F = g_f + (size_t)b * 65536 + (size_t)i * 256 + hb2 * 64;
    float fr[64];
#pragma unroll
    for (int q = 0; q < 16; q++) *(float4*)(fr + q * 4) = *(const float4*)(F + q * 4);
    __half* Uh = g_Uh + (size_t)b * 65536 + (size_t)i * 256 + hb2 * 64;
    for (int c = 0; c < 64; c += 2) {
        float a0 = 0.f, a1 = 0.f;
#pragma unroll
        for (int o = 0; o < 64; o++) { a0 = fmaf(fr[o], wgs[o][c], a0); a1 = fmaf(fr[o], wgs[o][c + 1], a1); }
        *(__half2*)(Uh + c) = __floats2half2_rn(a0, a1);
    }
    float bs = 0.f;
#pragma unroll
    for (int o = 0; o < 64; o++) bs = fmaf(fr[o], __ldg(&bg[o]), bs);
    g_bp[((size_t)b * 4 + hb2) * 256 + i] = bs;
}

// ---- K3: Y4h[f,i] = fp16( sum_mp x2[raw(mp), f] * U[i, mp] + beta[i] ) ----
__global__ void __launch_bounds__(256) k3(const float* __restrict__ x) {
    extern __shared__ uint32_t smu[];
    uint32_t* pAH = smu;
    float* sbeta = (float*)(smu + 4608);
    const int t = threadIdx.x, lane = t & 31, wid = t >> 5;
    const int wf = wid >> 2, wi = wid & 3, g = lane >> 2, tg = lane & 3;
    const int f0 = (blockIdx.x >> 1) * 128, i0 = (blockIdx.x & 1) * 128, b = blockIdx.y;
    const float* xp = x + (size_t)b * PB;
    const __half* Uhp = g_Uh + (size_t)b * 65536;
    if (t < 128) {
        int i = i0 + t;
        sbeta[t] = g_bp[((size_t)b * 4 + 0) * 256 + i] + g_bp[((size_t)b * 4 + 1) * 256 + i]
                 + g_bp[((size_t)b * 4 + 2) * 256 + i] + g_bp[((size_t)b * 4 + 3) * 256 + i];
    }
    const int kr = t >> 2, fq = (t & 3) * 32;
    float acc[4][4][4];
#pragma unroll
    for (int i = 0; i < 4; i++)
#pragma unroll
        for (int j = 0; j < 4; j++)
#pragma unroll
            for (int q = 0; q < 4; q++) acc[i][j][q] = 0.f;

    for (int ck = 0; ck < 4; ck++) {
        const float4* src = (const float4*)(xp + (size_t)(kr * 4 + ck) * KD + f0 + fq);
        float4 v[4];
#pragma unroll
        for (int q = 0; q < 4; q++) v[q] = src[q];
        __syncthreads();
#pragma unroll
        for (int q = 0; q < 4; q++)
#pragma unroll
            for (int j = 0; j < 4; j++) {
                int f = fq + q * 4 + j;
                ((__half*)pAH)[f * 72 + kr] = __float2half((&v[q].x)[j]);
            }
#pragma unroll
        for (int q = 0; q < 4; q++) v[q] = src[4 + q];
#pragma unroll
        for (int q = 0; q < 4; q++)
#pragma unroll
            for (int j = 0; j < 4; j++) {
                int f = fq + (4 + q) * 4 + j;
                ((__half*)pAH)[f * 72 + kr] = __float2half((&v[q].x)[j]);
            }
        __syncthreads();
#pragma unroll
        for (int kk = 0; kk < 4; kk++) {
            const int kh = kk * 8;
            const int kg = ck * 64 + kk * 16 + tg * 2;
            uint32_t Ah[4][4], Bh[4][2];
#pragma unroll
            for (int mt = 0; mt < 4; mt++) {
                int mr = wf * 64 + mt * 16;
                Ah[mt][0] = pAH[(mr + g) * 36 + kh + tg];
                Ah[mt][1] = pAH[(mr + g + 8) * 36 + kh + tg];
                Ah[mt][2] = pAH[(mr + g) * 36 + kh + tg + 4];
                Ah[mt][3] = pAH[(mr + g + 8) * 36 + kh + tg + 4];
            }
#pragma unroll
            for (int nt = 0; nt < 4; nt++) {
                int i = i0 + wi * 32 + nt * 8 + g;
                Bh[nt][0] = *(const uint32_t*)(Uhp + (size_t)i * 256 + kg);
                Bh[nt][1] = *(const uint32_t*)(Uhp + (size_t)i * 256 + kg + 8);
            }
#pragma unroll
            for (int mt = 0; mt < 4; mt++)
#pragma unroll
                for (int nt = 0; nt < 4; nt++)
                    hmma_hf(acc[mt][nt], Ah[mt], Bh[nt]);
        }
    }
    __half* Y = g_y4h + (size_t)b * PB;
#pragma unroll
    for (int mt = 0; mt < 4; mt++)
#pragma unroll
        for (int nt = 0; nt < 4; nt++) {
            int f = f0 + wf * 64 + mt * 16 + g;
            int il = wi * 32 + nt * 8 + tg * 2;
            float b0 = sbeta[il], b1 = sbeta[il + 1];
            int i = i0 + il;
            *(__half2*)(Y + (size_t)f * 256 + i) = __floats2half2_rn(acc[mt][nt][0] + b0, acc[mt][nt][1] + b1);
            *(__half2*)(Y + (size_t)(f + 8) * 256 + i) = __floats2half2_rn(acc[mt][nt][2] + b0, acc[mt][nt][3] + b1);
        }
}

// ---- K4: out = wW @ y4h + bW + x ----
__global__ void __launch_bounds__(256) k4(const float* __restrict__ wW, const float* __restrict__ bW,
                                          const float* __restrict__ x, float* __restrict__ out) {
    __shared__ uint32_t sWu[64 * 36];
    __shared__ uint32_t sYu[256 * 36];
    const int t = threadIdx.x, lane = t & 31, wid = t >> 5;
    const int wm = wid >> 2, wn = wid & 3, g = lane >> 2, tg = lane & 3;
    const int p0 = blockIdx.x * 256, b = blockIdx.y;
    for (int idx = t; idx < 4096; idx += 256) {
        int o = idx >> 6, c = idx & 63;
        ((__half*)sWu)[o * 72 + c] = __float2half(wW[idx]);
    }
    {
        const __half* Yg = g_y4h + (size_t)b * PB + p0;
        const int tp2 = (t & 127) * 2, co = (t >> 7) * 32;
        for (int c = 0; c < 32; c++) {
            __half2 v = *(const __half2*)(Yg + (size_t)(co + c) * 65536 + tp2);
            ((__half*)sYu)[tp2 * 72 + co + c] = v.x;
            ((__half*)sYu)[(tp2 + 1) * 72 + co + c] = v.y;
        }
    }
    __syncthreads();
    float acc[2][8][4];
#pragma unroll
    for (int i = 0; i < 2; i++)
#pragma unroll
        for (int j = 0; j < 8; j++)
#pragma unroll
            for (int q = 0; q < 4; q++) acc[i][j][q] = 0.f;
#pragma unroll
    for (int kk = 0; kk < 4; kk++) {
        const int kh = kk * 8;
        uint32_t A[2][4], B[8][2];
#pragma unroll
        for (int mt = 0; mt < 2; mt++) {
            int mr = wm * 32 + mt * 16;
            A[mt][0] = sWu[(mr + g) * 36 + kh + tg];
            A[mt][1] = sWu[(mr + g + 8) * 36 + kh + tg];
            A[mt][2] = sWu[(mr + g) * 36 + kh + tg + 4];
            A[mt][3] = sWu[(mr + g + 8) * 36 + kh + tg + 4];
        }
#pragma unroll
        for (int nt = 0; nt < 8; nt++) {
            int nr = wn * 64 + nt * 8 + g;
            B[nt][0] = sYu[nr * 36 + kh + tg];
            B[nt][1] = sYu[nr * 36 + kh + tg + 4];
        }
#pragma unroll
        for (int mt = 0; mt < 2; mt++)
#pragma unroll
            for (int nt = 0; nt < 8; nt++) hmma_hf(acc[mt][nt], A[mt], B[nt]);
    }
    const size_t xb = (size_t)b * PB;
#pragma unroll
    for (int mt = 0; mt < 2; mt++) {
        int o = wm * 32 + mt * 16 + g;
        float bw0 = __ldg(&bW[o]), bw1 = __ldg(&bW[o + 8]);
#pragma unroll
        for (int nt = 0; nt < 8; nt++) {
            int p = p0 + wn * 64 + nt * 8 + tg * 2;
            size_t e0 = xb + (size_t)o * 65536 + p;
            size_t e1 = xb + (size_t)(o + 8) * 65536 + p;
            float2 x0 = *(const float2*)(x + e0);
            float2 x1 = *(const float2*)(x + e1);
            *(float2*)(out + e0) = make_float2(acc[mt][nt][0] + bw0 + x0.x, acc[mt][nt][1] + bw0 + x0.y);
            *(float2*)(out + e1) = make_float2(acc[mt][nt][2] + bw1 + x1.x, acc[mt][nt][3] + bw1 + x1.y);
        }
    }
}

extern "C" void kernel_launch(void* const* d_in, const int* in_sizes, int n_in,
                              void* d_out, int out_size) {
    const float* x    = (const float*)d_in[0];
    const float* ref  = (const float*)d_in[1];
    const float* w_g  = (const float*)d_in[2];
    const float* b_g  = (const float*)d_in[3];
    const float* w_th = (const float*)d_in[4];
    const float* b_th = (const float*)d_in[5];
    const float* w_ph = (const float*)d_in[6];
    const float* b_ph = (const float*)d_in[7];
    const float* w_W  = (const float*)d_in[8];
    const float* b_W  = (const float*)d_in[9];
    float* out = (float*)d_out;

    cudaFuncSetAttribute(k1, cudaFuncAttributeMaxDynamicSharedMemorySize, 73728);

    kz         <<<8, 256>>>();
    k1         <<<dim3(4, 8, SPLIT), 256, 73728>>>(ref, x);
    kred       <<<512, 256>>>();
    k2a_f      <<<dim3(16, 8), 256>>>(w_th, b_th, w_ph, b_ph);   // launch #4 = profiled
    k2b_softmax<<<dim3(32, 8), 256>>>();
    k2c_u      <<<dim3(4, 8), 256>>>(w_g, b_g);
    k3         <<<dim3(256, 8), 256, 18944>>>(x);
    k4         <<<dim3(256, 8), 256>>>(w_W, b_W, x, out);
}

// round 17
// speedup vs baseline: 1.0093x; 1.0093x over previous
#include <cuda_runtime.h>
#include <cuda_bf16.h>
#include <cuda_fp16.h>
#include <cstdint>
#include <cstddef>

#define BATCH 8
#define PB    4194304
#define KD    16384
#define SPLIT 8

__device__ float g_part[(size_t)SPLIT * BATCH * 65536];
__device__ float g_red[(size_t)BATCH * 65536];
__device__ float g_sr[BATCH * 256];
__device__ float g_sx[BATCH * 256];
__device__ float g_f [BATCH * 65536];
__device__ __half g_Uh[BATCH * 65536];
__device__ float g_bp[BATCH * 4 * 256];
__device__ __half g_y4h[(size_t)BATCH * PB];

static __device__ __forceinline__ void hmma_bf(float* d, const uint32_t* a, const uint32_t* b) {
    asm volatile("mma.sync.aligned.m16n8k16.row.col.f32.bf16.bf16.f32 "
        "{%0,%1,%2,%3}, {%4,%5,%6,%7}, {%8,%9}, {%0,%1,%2,%3};"
        : "+f"(d[0]), "+f"(d[1]), "+f"(d[2]), "+f"(d[3])
        : "r"(a[0]), "r"(a[1]), "r"(a[2]), "r"(a[3]), "r"(b[0]), "r"(b[1]));
}
static __device__ __forceinline__ void hmma_hf(float* d, const uint32_t* a, const uint32_t* b) {
    asm volatile("mma.sync.aligned.m16n8k16.row.col.f32.f16.f16.f32 "
        "{%0,%1,%2,%3}, {%4,%5,%6,%7}, {%8,%9}, {%0,%1,%2,%3};"
        : "+f"(d[0]), "+f"(d[1]), "+f"(d[2]), "+f"(d[3])
        : "r"(a[0]), "r"(a[1]), "r"(a[2]), "r"(a[3]), "r"(b[0]), "r"(b[1]));
}
static __device__ __forceinline__ void pk(float x, float y, uint32_t& h, uint32_t& e) {
    uint32_t hv;
    asm("cvt.rn.bf16x2.f32 %0, %1, %2;" : "=r"(hv) : "f"(y), "f"(x));
    float hx = __uint_as_float(hv << 16);
    float hy = __uint_as_float(hv & 0xFFFF0000u);
    uint32_t ev;
    float ex = x - hx, ey = y - hy;
    asm("cvt.rn.bf16x2.f32 %0, %1, %2;" : "=r"(ev) : "f"(ey), "f"(ex));
    h = hv; e = ev;
}

__global__ void kz() {
    int i = blockIdx.x * 256 + threadIdx.x;
    g_sr[i] = 0.f; g_sx[i] = 0.f;
}

// ---- K1: G = ref2 @ x2^T, bf16 3-product, split-K, fused rowsums ----
__global__ void __launch_bounds__(256, 2) k1(const float* __restrict__ ref, const float* __restrict__ x) {
    extern __shared__ uint32_t smu[];
    uint32_t* pAH = smu;         uint32_t* pAE = smu + 4608;
    uint32_t* pBH = smu + 9216;  uint32_t* pBE = smu + 13824;
    const int t = threadIdx.x, lane = t & 31, wid = t >> 5;
    const int wm = wid >> 2, wn = wid & 3, g = lane >> 2, tg = lane & 3;
    const int mt_ = blockIdx.x >> 1, nt_ = blockIdx.x & 1, b = blockIdx.y, sp = blockIdx.z;
    const int m0 = mt_ * 128, n0 = nt_ * 128;
    const float* Ag = ref + (size_t)b * PB + (size_t)m0 * KD + sp * 2048;
    const float* Bg = x   + (size_t)b * PB + (size_t)n0 * KD + sp * 2048;
    const int r = t >> 1, kb = (t & 1) * 32;
    float sa = 0.f, sx = 0.f;
    float acc[4][4][4];
#pragma unroll
    for (int i = 0; i < 4; i++)
#pragma unroll
        for (int j = 0; j < 4; j++)
#pragma unroll
            for (int q = 0; q < 4; q++) acc[i][j][q] = 0.f;

    for (int ck = 0; ck < 32; ck++) {
        const float4* ap = (const float4*)(Ag + (size_t)r * KD + ck * 64 + kb);
        const float4* bp = (const float4*)(Bg + (size_t)r * KD + ck * 64 + kb);
        float4 va[4], vb[4];
#pragma unroll
        for (int q = 0; q < 4; q++) { va[q] = ap[q]; vb[q] = bp[q]; }
        __syncthreads();
#pragma unroll
        for (int q = 0; q < 4; q++) {
            sa += (va[q].x + va[q].y) + (va[q].z + va[q].w);
            sx += (vb[q].x + vb[q].y) + (vb[q].z + vb[q].w);
            uint32_t h0, e0, h1, e1;
            int ix = r * 36 + ((kb + q * 4) >> 1);
            pk(va[q].x, va[q].y, h0, e0); pk(va[q].z, va[q].w, h1, e1);
            pAH[ix] = h0; pAH[ix + 1] = h1; pAE[ix] = e0; pAE[ix + 1] = e1;
            pk(vb[q].x, vb[q].y, h0, e0); pk(vb[q].z, vb[q].w, h1, e1);
            pBH[ix] = h0; pBH[ix + 1] = h1; pBE[ix] = e0; pBE[ix + 1] = e1;
        }
#pragma unroll
        for (int q = 0; q < 4; q++) { va[q] = ap[4 + q]; vb[q] = bp[4 + q]; }
#pragma unroll
        for (int q = 0; q < 4; q++) {
            sa += (va[q].x + va[q].y) + (va[q].z + va[q].w);
            sx += (vb[q].x + vb[q].y) + (vb[q].z + vb[q].w);
            uint32_t h0, e0, h1, e1;
            int ix = r * 36 + ((kb + (4 + q) * 4) >> 1);
            pk(va[q].x, va[q].y, h0, e0); pk(va[q].z, va[q].w, h1, e1);
            pAH[ix] = h0; pAH[ix + 1] = h1; pAE[ix] = e0; pAE[ix + 1] = e1;
            pk(vb[q].x, vb[q].y, h0, e0); pk(vb[q].z, vb[q].w, h1, e1);
            pBH[ix] = h0; pBH[ix + 1] = h1; pBE[ix] = e0; pBE[ix + 1] = e1;
        }
        __syncthreads();
#pragma unroll
        for (int kk = 0; kk < 4; kk++) {
            const int kh = kk * 8;
            uint32_t Ah[4][4], Ae[4][4], Bh[4][2], Be[4][2];
#pragma unroll
            for (int mt = 0; mt < 4; mt++) {
                int mr = wm * 64 + mt * 16;
                Ah[mt][0] = pAH[(mr + g) * 36 + kh + tg];
                Ah[mt][1] = pAH[(mr + g + 8) * 36 + kh + tg];
                Ah[mt][2] = pAH[(mr + g) * 36 + kh + tg + 4];
                Ah[mt][3] = pAH[(mr + g + 8) * 36 + kh + tg + 4];
                Ae[mt][0] = pAE[(mr + g) * 36 + kh + tg];
                Ae[mt][1] = pAE[(mr + g + 8) * 36 + kh + tg];
                Ae[mt][2] = pAE[(mr + g) * 36 + kh + tg + 4];
                Ae[mt][3] = pAE[(mr + g + 8) * 36 + kh + tg + 4];
            }
#pragma unroll
            for (int nt = 0; nt < 4; nt++) {
                int nr = wn * 32 + nt * 8 + g;
                Bh[nt][0] = pBH[nr * 36 + kh + tg];
                Bh[nt][1] = pBH[nr * 36 + kh + tg + 4];
                Be[nt][0] = pBE[nr * 36 + kh + tg];
                Be[nt][1] = pBE[nr * 36 + kh + tg + 4];
            }
#pragma unroll
            for (int mt = 0; mt < 4; mt++)
#pragma unroll
                for (int nt = 0; nt < 4; nt++) {
                    hmma_bf(acc[mt][nt], Ah[mt], Bh[nt]);
                    hmma_bf(acc[mt][nt], Ah[mt], Be[nt]);
                    hmma_bf(acc[mt][nt], Ae[mt], Bh[nt]);
                }
        }
    }
    sa += __shfl_xor_sync(0xffffffffu, sa, 1);
    sx += __shfl_xor_sync(0xffffffffu, sx, 1);
    if ((t & 1) == 0) {
        if (nt_ == 0) atomicAdd(&g_sr[b * 256 + m0 + r], sa);
        if (mt_ == 0) atomicAdd(&g_sx[b * 256 + n0 + r], sx);
    }
    float* op = g_part + ((size_t)sp * BATCH + b) * 65536;
#pragma unroll
    for (int mt = 0; mt < 4; mt++)
#pragma unroll
        for (int nt = 0; nt < 4; nt++) {
            int row = m0 + wm * 64 + mt * 16 + g;
            int col = n0 + wn * 32 + nt * 8 + tg * 2;
            int rp = (row & 3) * 64 + (row >> 2);
            int cp = (col & 3) * 64 + (col >> 2);
            op[(size_t)rp * 256 + cp]            = acc[mt][nt][0];
            op[(size_t)rp * 256 + cp + 64]       = acc[mt][nt][1];
            op[(size_t)(rp + 2) * 256 + cp]      = acc[mt][nt][2];
            op[(size_t)(rp + 2) * 256 + cp + 64] = acc[mt][nt][3];
        }
}

// ---- KRED: g_red = sum_s g_part[s] ----
__global__ void kred() {
    const size_t i = ((size_t)blockIdx.x * 256 + threadIdx.x) * 4;
    float4 a = *(const float4*)(g_part + i);
#pragma unroll
    for (int s = 1; s < SPLIT; s++) {
        float4 v = *(const float4*)(g_part + (size_t)s * (BATCH * 65536) + i);
        a.x += v.x; a.y += v.y; a.z += v.z; a.w += v.w;
    }
    *(float4*)(g_red + i) = a;
}

// ---- K2a: f = Wth' G Wph'^T + bias rank-1 (ILP-4 chains) ----
__global__ void k2a_f(const float* __restrict__ wth, const float* __restrict__ bth,
                      const float* __restrict__ wph, const float* __restrict__ bph) {
    const int hb1 = blockIdx.x >> 2, hb2 = blockIdx.x & 3, b = blockIdx.y;
    __shared__ float S[64][64], T[64][64], ths[64], phs[64];
    const int t = threadIdx.x;
    for (int idx = t; idx < 4096; idx += 256) {
        int c = idx >> 6, cp = idx & 63;
        S[c][cp] = g_red[(size_t)b * 65536 + (size_t)(hb1 * 64 + c) * 256 + hb2 * 64 + cp];
    }
    __syncthreads();
    for (int idx = t; idx < 4096; idx += 256) {
        int ci = idx >> 6, cp = idx & 63;
        float a0 = 0.f, a1 = 0.f, a2 = 0.f, a3 = 0.f;
#pragma unroll
        for (int c = 0; c < 64; c += 4) {
            a0 = fmaf(__ldg(&wth[ci * 64 + c]),     S[c][cp],     a0);
            a1 = fmaf(__ldg(&wth[ci * 64 + c + 1]), S[c + 1][cp], a1);
            a2 = fmaf(__ldg(&wth[ci * 64 + c + 2]), S[c + 2][cp], a2);
            a3 = fmaf(__ldg(&wth[ci * 64 + c + 3]), S[c + 3][cp], a3);
        }
        T[ci][cp] = (a0 + a1) + (a2 + a3);
    }
    __syncthreads();
    if (t < 64) {
        float a = 0.f;
        for (int c = 0; c < 64; c++) a = fmaf(wth[t * 64 + c], g_sr[b * 256 + c * 4 + hb1], a);
        ths[t] = a;
    } else if (t < 128) {
        int ci = t - 64;
        float a = 0.f;
        for (int cp = 0; cp < 64; cp++) a = fmaf(wph[ci * 64 + cp], g_sx[b * 256 + cp * 4 + hb2], a);
        phs[ci] = a;
    }
    for (int idx = t; idx < 4096; idx += 256) S[idx & 63][idx >> 6] = wph[idx];
    __syncthreads();
    for (int idx = t; idx < 4096; idx += 256) {
        int c1 = idx >> 6, c2 = idx & 63;
        float a0 = 0.f, a1 = 0.f, a2 = 0.f, a3 = 0.f;
#pragma unroll
        for (int cp = 0; cp < 64; cp += 4) {
            a0 = fmaf(T[c1][cp],     S[cp][c2],     a0);
            a1 = fmaf(T[c1][cp + 1], S[cp + 1][c2], a1);
            a2 = fmaf(T[c1][cp + 2], S[cp + 2][c2], a2);
            a3 = fmaf(T[c1][cp + 3], S[cp + 3][c2], a3);
        }
        float a = (a0 + a1) + (a2 + a3);
        float bt = __ldg(&bth[c1]), bp = __ldg(&bph[c2]);
        a += bt * phs[c2] + ths[c1] * bp + 16384.f * bt * bp;
        g_f[(size_t)b * 65536 + (size_t)(c1 * 4 + hb1) * 256 + hb2 * 64 + c2] = a;
    }
}

__global__ void k2b_softmax() {
    const int b = blockIdx.y, col = blockIdx.x * 8 + (threadIdx.x >> 5), lane = threadIdx.x & 31;
    float* F = g_f + (size_t)b * 65536;
    float v[8];
#pragma unroll
    for (int s = 0; s < 8; s++) v[s] = F[(s * 32 + lane) * 256 + col];
    float m = v[0];
#pragma unroll
    for (int s = 1; s < 8; s++) m = fmaxf(m, v[s]);
#pragma unroll
    for (int o = 16; o > 0; o >>= 1) m = fmaxf(m, __shfl_xor_sync(0xffffffffu, m, o));
    float sum = 0.f;
#pragma unroll
    for (int s = 0; s < 8; s++) { v[s] = expf(v[s] - m); sum += v[s]; }
#pragma unroll
    for (int o = 16; o > 0; o >>= 1) sum += __shfl_xor_sync(0xffffffffu, sum, o);
    float rcp = 1.f / sum;
#pragma unroll
    for (int s = 0; s < 8; s++) F[(s * 32 + lane) * 256 + col] = v[s] * rcp;
}

// ---- K2c: U = fdiv * Wg-blockdiag -> fp16 (128 blocks, ILP-4); beta ----
__global__ void k2c_u(const float* __restrict__ wg, const float* __restrict__ bg) {
    const int hb2 = blockIdx.x & 3, ig = blockIdx.x >> 2, b = blockIdx.y;
    __shared__ float wgs[64][65];   // wgs[o][c], padded
    for (int idx = threadIdx.x; idx < 4096; idx += 256) wgs[idx >> 6][idx & 63] = wg[idx];
    __syncthreads();
    const int il = threadIdx.x & 63, cq = threadIdx.x >> 6;   // i-local, c-quarter
    const int i = ig * 64 + il;
    const float* F = g_f + (size_t)b * 65536 + (size_t)i * 256 + hb2 * 64;
    float fr[64];
#pragma unroll
    for (int q = 0; q < 16; q++) *(float4*)(fr + q * 4) = *(const float4*)(F + q * 4);
    __half* Uh = g_Uh + (size_t)b * 65536 + (size_t)i * 256 + hb2 * 64 + cq * 16;
#pragma unroll
    for (int c = 0; c < 16; c += 2) {
        float a0 = 0.f, a1 = 0.f, b0 = 0.f, b1 = 0.f;
#pragma unroll
        for (int o = 0; o < 64; o += 2) {
            a0 = fmaf(fr[o],     wgs[o][cq * 16 + c],         a0);
            a1 = fmaf(fr[o + 1], wgs[o + 1][cq * 16 + c],     a1);
            b0 = fmaf(fr[o],     wgs[o][cq * 16 + c + 1],     b0);
            b1 = fmaf(fr[o + 1], wgs[o + 1][cq * 16 + c + 1], b1);
        }
        *(__half2*)(Uh + c) = __floats2half2_rn(a0 + a1, b0 + b1);
    }
    if (cq == 0) {
        float bs0 = 0.f, bs1 = 0.f;
#pragma unroll
        for (int o = 0; o < 64; o += 2) {
            bs0 = fmaf(fr[o], __ldg(&bg[o]), bs0);
            bs1 = fmaf(fr[o + 1], __ldg(&bg[o + 1]), bs1);
        }
        g_bp[((size_t)b * 4 + hb2) * 256 + i] = bs0 + bs1;
    }
}

// ---- K3: Y4h[f,i] = fp16( sum_mp x2[raw(mp), f] * U[i, mp] + beta[i] ) ----
__global__ void __launch_bounds__(256) k3(const float* __restrict__ x) {
    extern __shared__ uint32_t smu[];
    uint32_t* pAH = smu;
    float* sbeta = (float*)(smu + 4608);
    const int t = threadIdx.x, lane = t & 31, wid = t >> 5;
    const int wf = wid >> 2, wi = wid & 3, g = lane >> 2, tg = lane & 3;
    const int f0 = (blockIdx.x >> 1) * 128, i0 = (blockIdx.x & 1) * 128, b = blockIdx.y;
    const float* xp = x + (size_t)b * PB;
    const __half* Uhp = g_Uh + (size_t)b * 65536;
    if (t < 128) {
        int i = i0 + t;
        sbeta[t] = g_bp[((size_t)b * 4 + 0) * 256 + i] + g_bp[((size_t)b * 4 + 1) * 256 + i]
                 + g_bp[((size_t)b * 4 + 2) * 256 + i] + g_bp[((size_t)b * 4 + 3) * 256 + i];
    }
    const int kr = t >> 2, fq = (t & 3) * 32;
    float acc[4][4][4];
#pragma unroll
    for (int i = 0; i < 4; i++)
#pragma unroll
        for (int j = 0; j < 4; j++)
#pragma unroll
            for (int q = 0; q < 4; q++) acc[i][j][q] = 0.f;

    for (int ck = 0; ck < 4; ck++) {
        const float4* src = (const float4*)(xp + (size_t)(kr * 4 + ck) * KD + f0 + fq);
        float4 v[4];
#pragma unroll
        for (int q = 0; q < 4; q++) v[q] = src[q];
        __syncthreads();
#pragma unroll
        for (int q = 0; q < 4; q++)
#pragma unroll
            for (int j = 0; j < 4; j++) {
                int f = fq + q * 4 + j;
                ((__half*)pAH)[f * 72 + kr] = __float2half((&v[q].x)[j]);
            }
#pragma unroll
        for (int q = 0; q < 4; q++) v[q] = src[4 + q];
#pragma unroll
        for (int q = 0; q < 4; q++)
#pragma unroll
            for (int j = 0; j < 4; j++) {
                int f = fq + (4 + q) * 4 + j;
                ((__half*)pAH)[f * 72 + kr] = __float2half((&v[q].x)[j]);
            }
        __syncthreads();
#pragma unroll
        for (int kk = 0; kk < 4; kk++) {
            const int kh = kk * 8;
            const int kg = ck * 64 + kk * 16 + tg * 2;
            uint32_t Ah[4][4], Bh[4][2];
#pragma unroll
            for (int mt = 0; mt < 4; mt++) {
                int mr = wf * 64 + mt * 16;
                Ah[mt][0] = pAH[(mr + g) * 36 + kh + tg];
                Ah[mt][1] = pAH[(mr + g + 8) * 36 + kh + tg];
                Ah[mt][2] = pAH[(mr + g) * 36 + kh + tg + 4];
                Ah[mt][3] = pAH[(mr + g + 8) * 36 + kh + tg + 4];
            }
#pragma unroll
            for (int nt = 0; nt < 4; nt++) {
                int i = i0 + wi * 32 + nt * 8 + g;
                Bh[nt][0] = *(const uint32_t*)(Uhp + (size_t)i * 256 + kg);
                Bh[nt][1] = *(const uint32_t*)(Uhp + (size_t)i * 256 + kg + 8);
            }
#pragma unroll
            for (int mt = 0; mt < 4; mt++)
#pragma unroll
                for (int nt = 0; nt < 4; nt++)
                    hmma_hf(acc[mt][nt], Ah[mt], Bh[nt]);
        }
    }
    __half* Y = g_y4h + (size_t)b * PB;
#pragma unroll
    for (int mt = 0; mt < 4; mt++)
#pragma unroll
        for (int nt = 0; nt < 4; nt++) {
            int f = f0 + wf * 64 + mt * 16 + g;
            int il = wi * 32 + nt * 8 + tg * 2;
            float b0 = sbeta[il], b1 = sbeta[il + 1];
            int i = i0 + il;
            *(__half2*)(Y + (size_t)f * 256 + i) = __floats2half2_rn(acc[mt][nt][0] + b0, acc[mt][nt][1] + b1);
            *(__half2*)(Y + (size_t)(f + 8) * 256 + i) = __floats2half2_rn(acc[mt][nt][2] + b0, acc[mt][nt][3] + b1);
        }
}

// ---- K4: out = wW @ y4h + bW + x ----
__global__ void __launch_bounds__(256) k4(const float* __restrict__ wW, const float* __restrict__ bW,
                                          const float* __restrict__ x, float* __restrict__ out) {
    __shared__ uint32_t sWu[64 * 36];
    __shared__ uint32_t sYu[256 * 36];
    const int t = threadIdx.x, lane = t & 31, wid = t >> 5;
    const int wm = wid >> 2, wn = wid & 3, g = lane >> 2, tg = lane & 3;
    const int p0 = blockIdx.x * 256, b = blockIdx.y;
    for (int idx = t; idx < 4096; idx += 256) {
        int o = idx >> 6, c = idx & 63;
        ((__half*)sWu)[o * 72 + c] = __float2half(wW[idx]);
    }
    {
        const __half* Yg = g_y4h + (size_t)b * PB + p0;
        const int tp2 = (t & 127) * 2, co = (t >> 7) * 32;
        for (int c = 0; c < 32; c++) {
            __half2 v = *(const __half2*)(Yg + (size_t)(co + c) * 65536 + tp2);
            ((__half*)sYu)[tp2 * 72 + co + c] = v.x;
            ((__half*)sYu)[(tp2 + 1) * 72 + co + c] = v.y;
        }
    }
    __syncthreads();
    float acc[2][8][4];
#pragma unroll
    for (int i = 0; i < 2; i++)
#pragma unroll
        for (int j = 0; j < 8; j++)
#pragma unroll
            for (int q = 0; q < 4; q++) acc[i][j][q] = 0.f;
#pragma unroll
    for (int kk = 0; kk < 4; kk++) {
        const int kh = kk * 8;
        uint32_t A[2][4], B[8][2];
#pragma unroll
        for (int mt = 0; mt < 2; mt++) {
            int mr = wm * 32 + mt * 16;
            A[mt][0] = sWu[(mr + g) * 36 + kh + tg];
            A[mt][1] = sWu[(mr + g + 8) * 36 + kh + tg];
            A[mt][2] = sWu[(mr + g) * 36 + kh + tg + 4];
            A[mt][3] = sWu[(mr + g + 8) * 36 + kh + tg + 4];
        }
#pragma unroll
        for (int nt = 0; nt < 8; nt++) {
            int nr = wn * 64 + nt * 8 + g;
            B[nt][0] = sYu[nr * 36 + kh + tg];
            B[nt][1] = sYu[nr * 36 + kh + tg + 4];
        }
#pragma unroll
        for (int mt = 0; mt < 2; mt++)
#pragma unroll
            for (int nt = 0; nt < 8; nt++) hmma_hf(acc[mt][nt], A[mt], B[nt]);
    }
    const size_t xb = (size_t)b * PB;
#pragma unroll
    for (int mt = 0; mt < 2; mt++) {
        int o = wm * 32 + mt * 16 + g;
        float bw0 = __ldg(&bW[o]), bw1 = __ldg(&bW[o + 8]);
#pragma unroll
        for (int nt = 0; nt < 8; nt++) {
            int p = p0 + wn * 64 + nt * 8 + tg * 2;
            size_t e0 = xb + (size_t)o * 65536 + p;
            size_t e1 = xb + (size_t)(o + 8) * 65536 + p;
            float2 x0 = *(const float2*)(x + e0);
            float2 x1 = *(const float2*)(x + e1);
            *(float2*)(out + e0) = make_float2(acc[mt][nt][0] + bw0 + x0.x, acc[mt][nt][1] + bw0 + x0.y);
            *(float2*)(out + e1) = make_float2(acc[mt][nt][2] + bw1 + x1.x, acc[mt][nt][3] + bw1 + x1.y);
        }
    }
}

extern "C" void kernel_launch(void* const* d_in, const int* in_sizes, int n_in,
                              void* d_out, int out_size) {
    const float* x    = (const float*)d_in[0];
    const float* ref  = (const float*)d_in[1];
    const float* w_g  = (const float*)d_in[2];
    const float* b_g  = (const float*)d_in[3];
    const float* w_th = (const float*)d_in[4];
    const float* b_th = (const float*)d_in[5];
    const float* w_ph = (const float*)d_in[6];
    const float* b_ph = (const float*)d_in[7];
    const float* w_W  = (const float*)d_in[8];
    const float* b_W  = (const float*)d_in[9];
    float* out = (float*)d_out;

    cudaFuncSetAttribute(k1, cudaFuncAttributeMaxDynamicSharedMemorySize, 73728);

    kz         <<<8, 256>>>();
    k1         <<<dim3(4, 8, SPLIT), 256, 73728>>>(ref, x);
    kred       <<<512, 256>>>();
    k2a_f      <<<dim3(16, 8), 256>>>(w_th, b_th, w_ph, b_ph);   // launch #4 = profiled
    k2b_softmax<<<dim3(32, 8), 256>>>();
    k2c_u      <<<dim3(16, 8), 256>>>(w_g, b_g);
    k3         <<<dim3(256, 8), 256, 18944>>>(x);
    k4         <<<dim3(256, 8), 256>>>(w_W, b_W, x, out);
}